// round 16
// baseline (speedup 1.0000x reference)
#include <cuda_runtime.h>
#include <cstdint>
#include <math.h>

#define NB 13
#define NW 118
#define MAXW 12
#define NPTS 2048
#define TAB_STRIDE (NPTS + 1)
#define XMIN (-8.0f)
#define XSPAN 16.0f
#define INV_H ((float)NPTS / XSPAN)   /* 128 */
#define H_STEP (XSPAN / (float)NPTS)

// tokens = 32*4096 = 131072 ; per block 16 tokens, 64 threads (4 thr/token)
#define TOK_PER_BLK 16
#define THREADS 64
#define NBLK 8192
#define TILE_FLOATS (TOK_PER_BLK * NW)        /* 1888 */
#define OUT_PER_BLK (TOK_PER_BLK * NB)        /* 208 */
#define SMEM_FLOATS (TILE_FLOATS + NB * MAXW) /* 2044 -> 8176B */

// Compile-time ragged structure (fixed by the problem)
__device__ constexpr int K_START[NB] = {5, 14, 23, 32, 41, 50, 59, 68, 77, 86, 95, 107, 115};
__device__ constexpr int K_LEN[NB]   = {9, 9, 9, 9, 9, 9, 9, 9, 9, 9, 12, 8, 3};

// Scratch (__device__ globals are the allowed scratch mechanism)
__device__ float g_table[NB * TAB_STRIDE];
__device__ float g_wts[NB * MAXW];

__device__ __forceinline__ float gelu_erf(float x) {
    return 0.5f * x * (1.0f + erff(x * 0.70710678118654752f));
}

__device__ __forceinline__ unsigned int smem_u32(const void* p) {
    return (unsigned int)__cvta_generic_to_shared(p);
}

// ---------------------------------------------------------------------------
// Kernel 1: build per-body tables (serial per-entry, proven shape).
// grid = (ceil(TAB_STRIDE/256), 13), block = 256
// ---------------------------------------------------------------------------
__global__ __launch_bounds__(256) void build_table_kernel(
    const float* __restrict__ agg_logits,
    const float* __restrict__ W1, const float* __restrict__ b1,
    const float* __restrict__ W2, const float* __restrict__ b2,
    const float* __restrict__ W3, const float* __restrict__ b3,
    const float* __restrict__ W4, const float* __restrict__ b4)
{
    const int c   = blockIdx.y;
    const int tid = threadIdx.x;

    // Fused softmax: block (0,0), lanes 0..12 compute g_wts once.
    if (blockIdx.x == 0 && c == 0 && tid < NB) {
        const int cc = tid;
        const int L = K_LEN[cc];
        float tmp[MAXW];
        float mx = -1e30f;
        for (int k = 0; k < L; k++) {
            tmp[k] = agg_logits[cc * MAXW + k];
            mx = fmaxf(mx, tmp[k]);
        }
        float s = 0.0f;
        for (int k = 0; k < L; k++) { tmp[k] = expf(tmp[k] - mx); s += tmp[k]; }
        const float inv = 1.0f / s;
        for (int k = 0; k < MAXW; k++)
            g_wts[cc * MAXW + k] = (k < L) ? tmp[k] * inv : 0.0f;
    }

    __shared__ float sW1[32], sB1[32], sB2[64], sB3[32], sW4[32];
    __shared__ float sW2[32 * 64];   // [i][o] row-major, o contiguous
    __shared__ float sW3[64 * 32];
    __shared__ float sB4;

    for (int i = tid; i < 2048; i += 256) {
        sW2[i] = W2[c * 2048 + i];
        sW3[i] = W3[c * 2048 + i];
    }
    if (tid < 32) {
        sW1[tid] = W1[c * 32 + tid];
        sB1[tid] = b1[c * 32 + tid];
        sB3[tid] = b3[c * 32 + tid];
        sW4[tid] = W4[c * 32 + tid];
    }
    if (tid < 64) sB2[tid] = b2[c * 64 + tid];
    if (tid == 0) sB4 = b4[c];
    __syncthreads();

    const int i = blockIdx.x * 256 + tid;
    if (i >= TAB_STRIDE) return;

    const float x = XMIN + H_STEP * (float)i;

    float h1[32];
#pragma unroll
    for (int j = 0; j < 32; j++)
        h1[j] = gelu_erf(fmaf(x, sW1[j], sB1[j]));

    float h2[64];
#pragma unroll
    for (int ob = 0; ob < 64; ob += 4) {
        float z0 = sB2[ob], z1 = sB2[ob + 1], z2 = sB2[ob + 2], z3 = sB2[ob + 3];
#pragma unroll
        for (int j = 0; j < 32; j++) {
            const float4 w = *reinterpret_cast<const float4*>(&sW2[j * 64 + ob]);
            z0 = fmaf(h1[j], w.x, z0);
            z1 = fmaf(h1[j], w.y, z1);
            z2 = fmaf(h1[j], w.z, z2);
            z3 = fmaf(h1[j], w.w, z3);
        }
        h2[ob]     = gelu_erf(z0);
        h2[ob + 1] = gelu_erf(z1);
        h2[ob + 2] = gelu_erf(z2);
        h2[ob + 3] = gelu_erf(z3);
    }

    float h3[32];
#pragma unroll
    for (int ob = 0; ob < 32; ob += 4) {
        float z0 = sB3[ob], z1 = sB3[ob + 1], z2 = sB3[ob + 2], z3 = sB3[ob + 3];
#pragma unroll
        for (int j = 0; j < 64; j++) {
            const float4 w = *reinterpret_cast<const float4*>(&sW3[j * 32 + ob]);
            z0 = fmaf(h2[j], w.x, z0);
            z1 = fmaf(h2[j], w.y, z1);
            z2 = fmaf(h2[j], w.z, z2);
            z3 = fmaf(h2[j], w.w, z3);
        }
        h3[ob]     = gelu_erf(z0);
        h3[ob + 1] = gelu_erf(z1);
        h3[ob + 2] = gelu_erf(z2);
        h3[ob + 3] = gelu_erf(z3);
    }

    float z = sB4;
#pragma unroll
    for (int j = 0; j < 32; j++)
        z = fmaf(h3[j], sW4[j], z);

    g_table[c * TAB_STRIDE + i] = tanhf(z);
}

// ---------------------------------------------------------------------------
// Templated per-thread body-range worker (fully unrolled at compile time).
// Writes HI-LO consecutive floats directly to global memory.
// ---------------------------------------------------------------------------
template<int LO, int HI>
__device__ __forceinline__ void process_bodies(
    const float* __restrict__ x, const float* __restrict__ wts,
    float* __restrict__ so_gmem)
{
#pragma unroll
    for (int c = LO; c < HI; c++) {
        float acc = 0.0f;
        const int st = K_START[c];
#pragma unroll
        for (int k = 0; k < K_LEN[c]; k++)
            acc = fmaf(x[st + k], wts[c * MAXW + k], acc);

        float t = (acc - XMIN) * INV_H;
        t = fminf(fmaxf(t, 0.0f), (float)NPTS - 0.001f);
        const int   i0 = (int)t;
        const float fr = t - (float)i0;
        const float* tb = g_table + c * TAB_STRIDE + i0;
        const float v0 = __ldg(tb);
        const float v1 = __ldg(tb + 1);
        so_gmem[c] = fmaf(fr, v1 - v0, v0);
    }
}

// ---------------------------------------------------------------------------
// Kernel 2: small 2-warp blocks, cp.async stage, direct gmem store.
// grid = 8192, block = 64, dynamic smem = SMEM_FLOATS*4 (8.2KB -> ~27 CTA/SM)
// ---------------------------------------------------------------------------
__global__ __launch_bounds__(THREADS) void main_kernel(
    const float* __restrict__ wf,
    float* __restrict__ out)
{
    extern __shared__ float smem[];
    float* sx  = smem;                        // [16 * 118] flat, token-major
    float* wts = smem + TILE_FLOATS;          // [13 * 12]

    const int tid = threadIdx.x;

    // Async tile stage: 1888 floats = 472 x 16B cp.async
    {
        const float4* g4 = reinterpret_cast<const float4*>(wf) +
                           (size_t)blockIdx.x * (TILE_FLOATS / 4);
        unsigned int sbase = smem_u32(sx);
#pragma unroll 2
        for (int i = tid; i < TILE_FLOATS / 4; i += THREADS) {
            asm volatile("cp.async.cg.shared.global [%0], [%1], 16;\n"
                         :: "r"(sbase + i * 16), "l"(g4 + i));
        }
        asm volatile("cp.async.commit_group;\n");
    }

    // Softmax weights while the tile is in flight (156 floats, 64 thr strided)
    for (int i = tid; i < NB * MAXW; i += THREADS)
        wts[i] = g_wts[i];

    asm volatile("cp.async.wait_group 0;\n" ::: "memory");
    __syncthreads();   // 2-warp barrier only

    // 4 threads per token: grp selects a compile-time body range
    const int tok = tid & (TOK_PER_BLK - 1);
    const int grp = tid >> 4;
    const float* x = sx + tok * NW;
    float* so = out + (size_t)blockIdx.x * OUT_PER_BLK + tok * NB;

    switch (grp) {
        case 0: process_bodies<0, 3>(x, wts, so);  break;
        case 1: process_bodies<3, 6>(x, wts, so);  break;
        case 2: process_bodies<6, 9>(x, wts, so);  break;
        default: process_bodies<9, 13>(x, wts, so); break;
    }
}

// ---------------------------------------------------------------------------
extern "C" void kernel_launch(void* const* d_in, const int* in_sizes, int n_in,
                              void* d_out, int out_size)
{
    const float* wf  = (const float*)d_in[0];
    const float* lg  = (const float*)d_in[1];
    const float* W1  = (const float*)d_in[2];
    const float* b1  = (const float*)d_in[3];
    const float* W2  = (const float*)d_in[4];
    const float* b2  = (const float*)d_in[5];
    const float* W3  = (const float*)d_in[6];
    const float* b3  = (const float*)d_in[7];
    const float* W4  = (const float*)d_in[8];
    const float* b4  = (const float*)d_in[9];
    float* out = (float*)d_out;

    (void)cudaFuncSetAttribute(main_kernel,
                               cudaFuncAttributeMaxDynamicSharedMemorySize,
                               SMEM_FLOATS * 4);

    dim3 bgrid((TAB_STRIDE + 255) / 256, NB);
    build_table_kernel<<<bgrid, 256>>>(lg, W1, b1, W2, b2, W3, b3, W4, b4);

    main_kernel<<<NBLK, THREADS, SMEM_FLOATS * 4>>>(wf, out);

    (void)in_sizes; (void)n_in; (void)out_size;
}

// round 17
// speedup vs baseline: 1.0465x; 1.0465x over previous
#include <cuda_runtime.h>
#include <cstdint>
#include <math.h>

#define NB 13
#define NW 118
#define MAXW 12
#define NPTS 2048
#define TAB_STRIDE (NPTS + 1)
#define XMIN (-8.0f)
#define XSPAN 16.0f
#define INV_H ((float)NPTS / XSPAN)   /* 128 */
#define H_STEP (XSPAN / (float)NPTS)

// tokens = 32*4096 = 131072 ; per block 32 tokens, 128 threads (4 thr/token)
#define TOK_PER_BLK 32
#define THREADS 128
#define NBLK 4096
#define TILE_FLOATS (TOK_PER_BLK * NW)        /* 3776 */
#define TILE_BYTES (TILE_FLOATS * 4)          /* 15104 */
#define OUT_PER_BLK (TOK_PER_BLK * NB)        /* 416 */
#define SMEM_FLOATS (TILE_FLOATS + OUT_PER_BLK + NB * MAXW)  /* 4348 */
#define SMEM_BYTES (SMEM_FLOATS * 4 + 16)     /* + mbarrier slot */

// Compile-time ragged structure (fixed by the problem)
__device__ constexpr int K_START[NB] = {5, 14, 23, 32, 41, 50, 59, 68, 77, 86, 95, 107, 115};
__device__ constexpr int K_LEN[NB]   = {9, 9, 9, 9, 9, 9, 9, 9, 9, 9, 12, 8, 3};

// Scratch (__device__ globals are the allowed scratch mechanism)
__device__ float g_table[NB * TAB_STRIDE];
__device__ float g_wts[NB * MAXW];

__device__ __forceinline__ float gelu_erf(float x) {
    return 0.5f * x * (1.0f + erff(x * 0.70710678118654752f));
}

__device__ __forceinline__ unsigned int smem_u32(const void* p) {
    return (unsigned int)__cvta_generic_to_shared(p);
}

// ---------------------------------------------------------------------------
// Kernel 1: build per-body tables (serial per-entry, proven shape).
// grid = (ceil(TAB_STRIDE/256), 13), block = 256
// ---------------------------------------------------------------------------
__global__ __launch_bounds__(256) void build_table_kernel(
    const float* __restrict__ agg_logits,
    const float* __restrict__ W1, const float* __restrict__ b1,
    const float* __restrict__ W2, const float* __restrict__ b2,
    const float* __restrict__ W3, const float* __restrict__ b3,
    const float* __restrict__ W4, const float* __restrict__ b4)
{
    const int c   = blockIdx.y;
    const int tid = threadIdx.x;

    // Fused softmax: block (0,0), lanes 0..12 compute g_wts once.
    if (blockIdx.x == 0 && c == 0 && tid < NB) {
        const int cc = tid;
        const int L = K_LEN[cc];
        float tmp[MAXW];
        float mx = -1e30f;
        for (int k = 0; k < L; k++) {
            tmp[k] = agg_logits[cc * MAXW + k];
            mx = fmaxf(mx, tmp[k]);
        }
        float s = 0.0f;
        for (int k = 0; k < L; k++) { tmp[k] = expf(tmp[k] - mx); s += tmp[k]; }
        const float inv = 1.0f / s;
        for (int k = 0; k < MAXW; k++)
            g_wts[cc * MAXW + k] = (k < L) ? tmp[k] * inv : 0.0f;
    }

    __shared__ float sW1[32], sB1[32], sB2[64], sB3[32], sW4[32];
    __shared__ float sW2[32 * 64];   // [i][o] row-major, o contiguous
    __shared__ float sW3[64 * 32];
    __shared__ float sB4;

    for (int i = tid; i < 2048; i += 256) {
        sW2[i] = W2[c * 2048 + i];
        sW3[i] = W3[c * 2048 + i];
    }
    if (tid < 32) {
        sW1[tid] = W1[c * 32 + tid];
        sB1[tid] = b1[c * 32 + tid];
        sB3[tid] = b3[c * 32 + tid];
        sW4[tid] = W4[c * 32 + tid];
    }
    if (tid < 64) sB2[tid] = b2[c * 64 + tid];
    if (tid == 0) sB4 = b4[c];
    __syncthreads();

    const int i = blockIdx.x * 256 + tid;
    if (i >= TAB_STRIDE) return;

    const float x = XMIN + H_STEP * (float)i;

    float h1[32];
#pragma unroll
    for (int j = 0; j < 32; j++)
        h1[j] = gelu_erf(fmaf(x, sW1[j], sB1[j]));

    float h2[64];
#pragma unroll
    for (int ob = 0; ob < 64; ob += 4) {
        float z0 = sB2[ob], z1 = sB2[ob + 1], z2 = sB2[ob + 2], z3 = sB2[ob + 3];
#pragma unroll
        for (int j = 0; j < 32; j++) {
            const float4 w = *reinterpret_cast<const float4*>(&sW2[j * 64 + ob]);
            z0 = fmaf(h1[j], w.x, z0);
            z1 = fmaf(h1[j], w.y, z1);
            z2 = fmaf(h1[j], w.z, z2);
            z3 = fmaf(h1[j], w.w, z3);
        }
        h2[ob]     = gelu_erf(z0);
        h2[ob + 1] = gelu_erf(z1);
        h2[ob + 2] = gelu_erf(z2);
        h2[ob + 3] = gelu_erf(z3);
    }

    float h3[32];
#pragma unroll
    for (int ob = 0; ob < 32; ob += 4) {
        float z0 = sB3[ob], z1 = sB3[ob + 1], z2 = sB3[ob + 2], z3 = sB3[ob + 3];
#pragma unroll
        for (int j = 0; j < 64; j++) {
            const float4 w = *reinterpret_cast<const float4*>(&sW3[j * 32 + ob]);
            z0 = fmaf(h2[j], w.x, z0);
            z1 = fmaf(h2[j], w.y, z1);
            z2 = fmaf(h2[j], w.z, z2);
            z3 = fmaf(h2[j], w.w, z3);
        }
        h3[ob]     = gelu_erf(z0);
        h3[ob + 1] = gelu_erf(z1);
        h3[ob + 2] = gelu_erf(z2);
        h3[ob + 3] = gelu_erf(z3);
    }

    float z = sB4;
#pragma unroll
    for (int j = 0; j < 32; j++)
        z = fmaf(h3[j], sW4[j], z);

    g_table[c * TAB_STRIDE + i] = tanhf(z);
}

// ---------------------------------------------------------------------------
// Templated per-thread body-range worker (fully unrolled at compile time)
// ---------------------------------------------------------------------------
template<int LO, int HI>
__device__ __forceinline__ void process_bodies(
    const float* __restrict__ x, const float* __restrict__ wts,
    float* __restrict__ so)
{
#pragma unroll
    for (int c = LO; c < HI; c++) {
        float acc = 0.0f;
        const int st = K_START[c];
#pragma unroll
        for (int k = 0; k < K_LEN[c]; k++)
            acc = fmaf(x[st + k], wts[c * MAXW + k], acc);

        float t = (acc - XMIN) * INV_H;
        t = fminf(fmaxf(t, 0.0f), (float)NPTS - 0.001f);
        const int   i0 = (int)t;
        const float fr = t - (float)i0;
        const float* tb = g_table + c * TAB_STRIDE + i0;
        const float v0 = __ldg(tb);
        const float v1 = __ldg(tb + 1);
        so[c] = fmaf(fr, v1 - v0, v0);
    }
}

// ---------------------------------------------------------------------------
// Kernel 2: ONE bulk-async copy per block (no per-thread LDGSTS), compute,
// smem-staged coalesced store.  grid = 4096, block = 128.
// ---------------------------------------------------------------------------
__global__ __launch_bounds__(THREADS) void main_kernel(
    const float* __restrict__ wf,
    float* __restrict__ out)
{
    extern __shared__ float smem[];
    float* sx   = smem;                       // [32 * 118] flat, token-major
    float* sout = smem + TILE_FLOATS;         // [32 * 13]
    float* wts  = sout + OUT_PER_BLK;         // [13 * 12]
    unsigned long long* mbar =
        reinterpret_cast<unsigned long long*>(wts + NB * MAXW);  // 8B aligned

    const int tid = threadIdx.x;
    const unsigned int mb = smem_u32(mbar);

    if (tid == 0) {
        asm volatile("mbarrier.init.shared.b64 [%0], 1;" :: "r"(mb) : "memory");
    }
    __syncthreads();

    if (tid == 0) {
        const char* gsrc = reinterpret_cast<const char*>(wf) +
                           (size_t)blockIdx.x * TILE_BYTES;
        asm volatile("mbarrier.arrive.expect_tx.shared.b64 _, [%0], %1;"
                     :: "r"(mb), "r"((unsigned)TILE_BYTES) : "memory");
        asm volatile("cp.async.bulk.shared::cta.global.mbarrier::complete_tx::bytes "
                     "[%0], [%1], %2, [%3];"
                     :: "r"(smem_u32(sx)), "l"(gsrc),
                        "r"((unsigned)TILE_BYTES), "r"(mb) : "memory");
    }

    // Softmax weights while the bulk copy is in flight
    for (int i = tid; i < NB * MAXW; i += THREADS)
        wts[i] = g_wts[i];

    // Wait for the bulk copy (phase 0)
    {
        asm volatile(
            "{\n\t"
            ".reg .pred P1;\n\t"
            "WAIT_%=:\n\t"
            "mbarrier.try_wait.parity.acquire.cta.shared::cta.b64 P1, [%0], 0;\n\t"
            "@P1 bra.uni DONE_%=;\n\t"
            "bra.uni WAIT_%=;\n\t"
            "DONE_%=:\n\t"
            "}"
            :: "r"(mb) : "memory");
    }
    __syncthreads();   // also orders the wts writes

    // 4 threads per token: grp selects a compile-time body range
    const int tok = tid & (TOK_PER_BLK - 1);
    const int grp = tid >> 5;
    const float* x = sx + tok * NW;
    float* so = sout + tok * NB;

    switch (grp) {
        case 0: process_bodies<0, 3>(x, wts, so);  break;
        case 1: process_bodies<3, 6>(x, wts, so);  break;
        case 2: process_bodies<6, 9>(x, wts, so);  break;
        default: process_bodies<9, 13>(x, wts, so); break;
    }
    __syncthreads();

    // Coalesced float4 output store: 416 floats = 104 float4 per block
    float4* ob4 = reinterpret_cast<float4*>(out + (size_t)blockIdx.x * OUT_PER_BLK);
    const float4* so4 = reinterpret_cast<const float4*>(sout);
    if (tid < OUT_PER_BLK / 4)
        ob4[tid] = so4[tid];
}

// ---------------------------------------------------------------------------
extern "C" void kernel_launch(void* const* d_in, const int* in_sizes, int n_in,
                              void* d_out, int out_size)
{
    const float* wf  = (const float*)d_in[0];
    const float* lg  = (const float*)d_in[1];
    const float* W1  = (const float*)d_in[2];
    const float* b1  = (const float*)d_in[3];
    const float* W2  = (const float*)d_in[4];
    const float* b2  = (const float*)d_in[5];
    const float* W3  = (const float*)d_in[6];
    const float* b3  = (const float*)d_in[7];
    const float* W4  = (const float*)d_in[8];
    const float* b4  = (const float*)d_in[9];
    float* out = (float*)d_out;

    (void)cudaFuncSetAttribute(main_kernel,
                               cudaFuncAttributeMaxDynamicSharedMemorySize,
                               SMEM_BYTES);

    dim3 bgrid((TAB_STRIDE + 255) / 256, NB);
    build_table_kernel<<<bgrid, 256>>>(lg, W1, b1, W2, b2, W3, b3, W4, b4);

    main_kernel<<<NBLK, THREADS, SMEM_BYTES>>>(wf, out);

    (void)in_sizes; (void)n_in; (void)out_size;
}